// round 14
// baseline (speedup 1.0000x reference)
#include <cuda_runtime.h>
#include <cuda_fp16.h>

#define PLANE 256
#define TW 64
#define TH 128
#define PKROWS 130         /* packed rows: pk[r] lanes = (row r-3, row r+1) rel ty0 */
#define SSTRIDE 72         /* half2 per packed row; 288B, 16B-aligned rows */
#define NQ 18              /* column quads per row (72/4) */
#define MAXVAL 10000.0f

__device__ __forceinline__ __half2 h2_from_u32(unsigned u) {
    __half2 h; *(unsigned*)&h = u; return h;
}

__device__ __forceinline__ void load_window(const __half2 (*pk)[SSTRIDE],
                                            int row, int oc, __half2 v[12])
{
    const uint4* rp = (const uint4*)&pk[row][oc];   // 16B-aligned, 3x LDS.128
    uint4 u0 = rp[0], u1 = rp[1], u2 = rp[2];
    v[0] = h2_from_u32(u0.x); v[1]  = h2_from_u32(u0.y);
    v[2] = h2_from_u32(u0.z); v[3]  = h2_from_u32(u0.w);
    v[4] = h2_from_u32(u1.x); v[5]  = h2_from_u32(u1.y);
    v[6] = h2_from_u32(u1.z); v[7]  = h2_from_u32(u1.w);
    v[8] = h2_from_u32(u2.x); v[9]  = h2_from_u32(u2.y);
    v[10]= h2_from_u32(u2.z); v[11] = h2_from_u32(u2.w);
}

// 7 taps with weight row w[t] (t increasing with dx). REV=1 uses w[6-t]
// (w(dy,dx) = w(-dy,-dx) mirror). SKIPC=1 skips the center tap (dy==0).
template<int REV, int SKIPC>
__device__ __forceinline__ void taps7(const __half2 v[12], const __half2 w[8],
                                      __half2 acc[4])
{
#pragma unroll
    for (int t = 0; t < 7; t++) {
        if (SKIPC && t == 3) continue;
        const __half2 wv = REV ? w[6 - t] : w[t];
#pragma unroll
        for (int c = 0; c < 4; c++)
            acc[c] = __hmax2(acc[c], __hadd2(v[c + t + 1], wv));
    }
}

__device__ __forceinline__ void load_wrow(const __half2* wsh, int row, __half2 w[8])
{
    uint4 a = *(const uint4*)&wsh[row * 8];
    uint4 b = *(const uint4*)&wsh[row * 8 + 4];
    w[0] = h2_from_u32(a.x); w[1] = h2_from_u32(a.y);
    w[2] = h2_from_u32(a.z); w[3] = h2_from_u32(a.w);
    w[4] = h2_from_u32(b.x); w[5] = h2_from_u32(b.y);
    w[6] = h2_from_u32(b.z); w[7] = h2_from_u32(b.w);
}

// Outer pass: dy in {-3,-2,+2,+3}. Packed row R = j + dy + 3, j = 0..3.
// Windows R0..R9, each feeding 1-2 (j,dy) pairs.
__device__ __forceinline__ void pgroup_outer(const __half2 (*pk)[SSTRIDE],
                                             const __half2* wsh,
                                             int orow, int oc,
                                             __half2 acc[4][4])
{
    __half2 w3[8], w2[8];
    load_wrow(wsh, 0, w3);     // dy = -3
    load_wrow(wsh, 1, w2);     // dy = -2
    __half2 v[12];

    load_window(pk, orow + 0, oc, v);
    taps7<0,0>(v, w3, acc[0]);
    load_window(pk, orow + 1, oc, v);
    taps7<0,0>(v, w3, acc[1]);  taps7<0,0>(v, w2, acc[0]);
    load_window(pk, orow + 2, oc, v);
    taps7<0,0>(v, w3, acc[2]);  taps7<0,0>(v, w2, acc[1]);
    load_window(pk, orow + 3, oc, v);
    taps7<0,0>(v, w3, acc[3]);  taps7<0,0>(v, w2, acc[2]);
    load_window(pk, orow + 4, oc, v);
    taps7<0,0>(v, w2, acc[3]);
    load_window(pk, orow + 5, oc, v);
    taps7<1,0>(v, w2, acc[0]);
    load_window(pk, orow + 6, oc, v);
    taps7<1,0>(v, w2, acc[1]);  taps7<1,0>(v, w3, acc[0]);
    load_window(pk, orow + 7, oc, v);
    taps7<1,0>(v, w2, acc[2]);  taps7<1,0>(v, w3, acc[1]);
    load_window(pk, orow + 8, oc, v);
    taps7<1,0>(v, w2, acc[3]);  taps7<1,0>(v, w3, acc[2]);
    load_window(pk, orow + 9, oc, v);
    taps7<1,0>(v, w3, acc[3]);
}

// Middle pass: dy in {-1,0,+1}. Windows R2..R7, each feeding 1-3 (j,dy) pairs.
__device__ __forceinline__ void pgroup_mid(const __half2 (*pk)[SSTRIDE],
                                           const __half2* wsh,
                                           int orow, int oc,
                                           __half2 acc[4][4])
{
    __half2 w1[8], w0[8];
    load_wrow(wsh, 2, w1);     // dy = -1
    load_wrow(wsh, 3, w0);     // dy =  0
    __half2 v[12];

    load_window(pk, orow + 2, oc, v);
    taps7<0,0>(v, w1, acc[0]);
    load_window(pk, orow + 3, oc, v);
    taps7<0,0>(v, w1, acc[1]);  taps7<0,1>(v, w0, acc[0]);
    load_window(pk, orow + 4, oc, v);
    taps7<0,0>(v, w1, acc[2]);  taps7<0,1>(v, w0, acc[1]);  taps7<1,0>(v, w1, acc[0]);
    load_window(pk, orow + 5, oc, v);
    taps7<0,0>(v, w1, acc[3]);  taps7<0,1>(v, w0, acc[2]);  taps7<1,0>(v, w1, acc[1]);
    load_window(pk, orow + 6, oc, v);
    taps7<0,1>(v, w0, acc[3]);  taps7<1,0>(v, w1, acc[2]);
    load_window(pk, orow + 7, oc, v);
    taps7<1,0>(v, w1, acc[3]);
}

__global__ __launch_bounds__(256, 4)
void quad_morpho_kernel(const float* __restrict__ x,
                        const float* __restrict__ k1,
                        const float* __restrict__ k2,
                        const float* __restrict__ k3,
                        float* __restrict__ out)
{
    __shared__ alignas(16) __half2 pk[PKROWS][SSTRIDE];
    __shared__ alignas(16) __half2 wsh[4 * 8];   // rows dy=-3,-2,-1,0 (padded to 8)

    const int plane = blockIdx.z;
    const int tx0 = blockIdx.x * TW;
    const int ty0 = blockIdx.y * TH;
    const float* xp = x + (size_t)plane * (PLANE * PLANE);
    float* op = out + (size_t)plane * (PLANE * PLANE);
    const int tid = threadIdx.x;

    // ---- Weight table (dy = -3..0 only; +dy rows are t-reversed mirrors).
    // Max of the convex-along-axes quadratic over the 7x7 grid is at a corner. ----
    if (tid < 32) {
        const int row = tid >> 3;            // 0..3 -> dy = row - 3
        const int t = tid & 7;               // 0..7 (7 = pad)
        const float A = k1[0], B = k2[0], C = k3[0];
        const float q_pp = 9.0f * A + 18.0f * B + 9.0f * C;
        const float q_pm = 9.0f * A - 18.0f * B + 9.0f * C;
        const float inv_m = 1.0f / fmaxf(q_pp, q_pm);
        const int dy = row - 3;
        const int dx = t - 3;
        float wv = -(A * (float)(dx * dx) + 2.0f * B * (float)(dx * dy)
                     + C * (float)(dy * dy)) * inv_m;
        if (t == 7) wv = 0.0f;               // pad slot
        wsh[tid] = __float2half2_rn(wv);
    }

    // ---- Packed tile fill. smem col c <-> global col tx0 + c - 4 (left halo 4
    // keeps quads 16B-aligned). pk[r][c] = half2(x[ty0+r-3], x[ty0+r+1]). ----
    for (int i = tid; i < PKROWS * NQ; i += 256) {
        const int r = i / NQ;
        const int q = i - r * NQ;
        const int gc = tx0 + q * 4 - 4;
        const int gr0 = ty0 + r - 3;
        const int gr1 = gr0 + 4;
        const bool r0in = (unsigned)gr0 < PLANE;
        const bool r1in = (unsigned)gr1 < PLANE;
        float4 a = make_float4(-MAXVAL, -MAXVAL, -MAXVAL, -MAXVAL);
        float4 b = a;
        if (gc >= 0 && gc <= PLANE - 4) {
            if (r0in) a = *(const float4*)&xp[gr0 * PLANE + gc];
            if (r1in) b = *(const float4*)&xp[gr1 * PLANE + gc];
        } else {
            float* ap = &a.x; float* bp = &b.x;
#pragma unroll
            for (int e = 0; e < 4; e++) {
                const int gce = gc + e;
                if ((unsigned)gce < PLANE) {
                    if (r0in) ap[e] = xp[gr0 * PLANE + gce];
                    if (r1in) bp[e] = xp[gr1 * PLANE + gce];
                }
            }
        }
        __half2 h0 = __floats2half2_rn(a.x, b.x);
        __half2 h1 = __floats2half2_rn(a.y, b.y);
        __half2 h2v = __floats2half2_rn(a.z, b.z);
        __half2 h3 = __floats2half2_rn(a.w, b.w);
        uint4 st;
        st.x = *(unsigned*)&h0; st.y = *(unsigned*)&h1;
        st.z = *(unsigned*)&h2v; st.w = *(unsigned*)&h3;
        *(uint4*)&pk[r][q * 4] = st;       // 16B-aligned STS.128
    }
    __syncthreads();

    // ---- Thread tile: 4 half2-cols x 4 j-slots (8 rows: lanes (j, j+4)). ----
    const int txg = tid & 15;
    const int tyg = tid >> 4;            // 0..15
    const int oc = txg * 4;              // tile-local col base
    const int orow = tyg * 8;            // tile-local row base (0..120)

    __half2 acc[4][4];
    const __half2 NEG = __float2half2_rn(-60000.0f);
#pragma unroll
    for (int j = 0; j < 4; j++)
#pragma unroll
        for (int c = 0; c < 4; c++) acc[j][c] = NEG;

    pgroup_outer(pk, wsh, orow, oc, acc);
    pgroup_mid(pk, wsh, orow, oc, acc);

    // ---- Store: lane0 -> row y, lane1 -> row y+4; float4 per row (aligned). ----
#pragma unroll
    for (int j = 0; j < 4; j++) {
        const int y0 = ty0 + orow + j;
        const int cg = tx0 + oc;
        float4 lo, hi;
        lo.x = __low2float(acc[j][0]);  lo.y = __low2float(acc[j][1]);
        lo.z = __low2float(acc[j][2]);  lo.w = __low2float(acc[j][3]);
        hi.x = __high2float(acc[j][0]); hi.y = __high2float(acc[j][1]);
        hi.z = __high2float(acc[j][2]); hi.w = __high2float(acc[j][3]);
        *(float4*)&op[y0 * PLANE + cg]       = lo;
        *(float4*)&op[(y0 + 4) * PLANE + cg] = hi;
    }
}

extern "C" void kernel_launch(void* const* d_in, const int* in_sizes, int n_in,
                              void* d_out, int out_size)
{
    const float* x  = (const float*)d_in[0];
    const float* k1 = (const float*)d_in[1];
    const float* k2 = (const float*)d_in[2];
    const float* k3 = (const float*)d_in[3];
    float* out = (float*)d_out;

    (void)in_sizes; (void)n_in; (void)out_size;

    dim3 block(256, 1, 1);
    dim3 grid(PLANE / TW, PLANE / TH, 8 * 64);
    quad_morpho_kernel<<<grid, block>>>(x, k1, k2, k3, out);
}

// round 15
// speedup vs baseline: 1.5399x; 1.5399x over previous
#include <cuda_runtime.h>
#include <cuda_fp16.h>

#define PLANE 256
#define TW 64
#define TH 64
#define PKROWS 66          /* packed rows: pk[r] lanes = (row r-3, row r+1) rel ty0 */
#define SSTRIDE 72         /* half2 per packed row; 288B, 16B-aligned rows */
#define NQ 18              /* column quads per row (72/4) */
#define MAXVAL 10000.0f

__device__ __forceinline__ __half2 h2_from_u32(unsigned u) {
    __half2 h; *(unsigned*)&h = u; return h;
}

__device__ __forceinline__ void load_window(const __half2 (*pk)[SSTRIDE],
                                            int row, int oc, __half2 v[12])
{
    const uint4* rp = (const uint4*)&pk[row][oc];   // 16B-aligned, 3x LDS.128
    uint4 u0 = rp[0], u1 = rp[1], u2 = rp[2];
    v[0] = h2_from_u32(u0.x); v[1]  = h2_from_u32(u0.y);
    v[2] = h2_from_u32(u0.z); v[3]  = h2_from_u32(u0.w);
    v[4] = h2_from_u32(u1.x); v[5]  = h2_from_u32(u1.y);
    v[6] = h2_from_u32(u1.z); v[7]  = h2_from_u32(u1.w);
    v[8] = h2_from_u32(u2.x); v[9]  = h2_from_u32(u2.y);
    v[10]= h2_from_u32(u2.z); v[11] = h2_from_u32(u2.w);
}

__device__ __forceinline__ void load_wrow(const __half2* wsh, int row, __half2 w[8])
{
    uint4 a = *(const uint4*)&wsh[row * 8];        // broadcast LDS.128 x2
    uint4 b = *(const uint4*)&wsh[row * 8 + 4];
    w[0] = h2_from_u32(a.x); w[1] = h2_from_u32(a.y);
    w[2] = h2_from_u32(a.z); w[3] = h2_from_u32(a.w);
    w[4] = h2_from_u32(b.x); w[5] = h2_from_u32(b.y);
    w[6] = h2_from_u32(b.z); w[7] = h2_from_u32(b.w);
}

// 7 taps with weight row w[t]. REV=1 uses w[6-t] (w(dy,dx)=w(-dy,-dx) mirror).
// SKIPC=1 skips the center tap (dy==0 row).
template<int REV, int SKIPC>
__device__ __forceinline__ void taps7(const __half2 v[12], const __half2 w[8],
                                      __half2 acc[4])
{
#pragma unroll
    for (int t = 0; t < 7; t++) {
        if (SKIPC && t == 3) continue;
        const __half2 wv = REV ? w[6 - t] : w[t];
#pragma unroll
        for (int c = 0; c < 4; c++)
            acc[c] = __hmax2(acc[c], __hadd2(v[c + t + 1], wv));
    }
}

// Subpass for |dy| = M: only ONE 8-reg weight row live at a time (the key to
// fitting 6 CTAs). Output j (0..1) with dy=-M reads packed row j+3-M; dy=+M
// reads j+3+M with t-reversed weights. M=0 applies once with center skip.
template<int M>
__device__ __forceinline__ void subpass(const __half2 (*pk)[SSTRIDE],
                                        const __half2* wsh,
                                        int orow, int oc,
                                        __half2 acc[2][4])
{
    __half2 w[8];
    load_wrow(wsh, 3 - M, w);      // row for dy = -M
    __half2 v[12];

    load_window(pk, orow + 3 - M, oc, v);
    if (M == 0) taps7<0,1>(v, w, acc[0]); else taps7<0,0>(v, w, acc[0]);
    load_window(pk, orow + 4 - M, oc, v);
    if (M == 0) taps7<0,1>(v, w, acc[1]); else taps7<0,0>(v, w, acc[1]);

    if (M > 0) {
        load_window(pk, orow + 3 + M, oc, v);
        taps7<1,0>(v, w, acc[0]);
        load_window(pk, orow + 4 + M, oc, v);
        taps7<1,0>(v, w, acc[1]);
    }
}

__global__ __launch_bounds__(256, 6)
void quad_morpho_kernel(const float* __restrict__ x,
                        const float* __restrict__ k1,
                        const float* __restrict__ k2,
                        const float* __restrict__ k3,
                        float* __restrict__ out)
{
    __shared__ alignas(16) __half2 pk[PKROWS][SSTRIDE];
    __shared__ alignas(16) __half2 wsh[4 * 8];   // rows dy=-3,-2,-1,0 (padded to 8)

    const int plane = blockIdx.z;
    const int tx0 = blockIdx.x * TW;
    const int ty0 = blockIdx.y * TH;
    const float* xp = x + (size_t)plane * (PLANE * PLANE);
    float* op = out + (size_t)plane * (PLANE * PLANE);
    const int tid = threadIdx.x;

    // ---- Weight table (dy = -3..0; +dy rows are t-reversed mirrors). Max of
    // the convex-along-axes quadratic over the 7x7 grid is at a corner. ----
    if (tid < 32) {
        const int row = tid >> 3;            // 0..3 -> dy = row - 3
        const int t = tid & 7;               // 0..7 (7 = pad)
        const float A = k1[0], B = k2[0], C = k3[0];
        const float q_pp = 9.0f * A + 18.0f * B + 9.0f * C;
        const float q_pm = 9.0f * A - 18.0f * B + 9.0f * C;
        const float inv_m = 1.0f / fmaxf(q_pp, q_pm);
        const int dy = row - 3;
        const int dx = t - 3;
        float wv = -(A * (float)(dx * dx) + 2.0f * B * (float)(dx * dy)
                     + C * (float)(dy * dy)) * inv_m;
        if (t == 7) wv = 0.0f;               // pad slot
        wsh[tid] = __float2half2_rn(wv);
    }

    // ---- Packed tile fill. smem col c <-> global col tx0 + c - 4 (left halo 4
    // keeps quads 16B-aligned). pk[r][c] = half2(x[ty0+r-3], x[ty0+r+1]). ----
    for (int i = tid; i < PKROWS * NQ; i += 256) {
        const int r = i / NQ;
        const int q = i - r * NQ;
        const int gc = tx0 + q * 4 - 4;
        const int gr0 = ty0 + r - 3;
        const int gr1 = gr0 + 4;
        const bool r0in = (unsigned)gr0 < PLANE;
        const bool r1in = (unsigned)gr1 < PLANE;
        float4 a = make_float4(-MAXVAL, -MAXVAL, -MAXVAL, -MAXVAL);
        float4 b = a;
        if (gc >= 0 && gc <= PLANE - 4) {
            if (r0in) a = *(const float4*)&xp[gr0 * PLANE + gc];
            if (r1in) b = *(const float4*)&xp[gr1 * PLANE + gc];
        } else {
            float* ap = &a.x; float* bp = &b.x;
#pragma unroll
            for (int e = 0; e < 4; e++) {
                const int gce = gc + e;
                if ((unsigned)gce < PLANE) {
                    if (r0in) ap[e] = xp[gr0 * PLANE + gce];
                    if (r1in) bp[e] = xp[gr1 * PLANE + gce];
                }
            }
        }
        __half2 h0 = __floats2half2_rn(a.x, b.x);
        __half2 h1 = __floats2half2_rn(a.y, b.y);
        __half2 h2v = __floats2half2_rn(a.z, b.z);
        __half2 h3 = __floats2half2_rn(a.w, b.w);
        uint4 st;
        st.x = *(unsigned*)&h0; st.y = *(unsigned*)&h1;
        st.z = *(unsigned*)&h2v; st.w = *(unsigned*)&h3;
        *(uint4*)&pk[r][q * 4] = st;       // 16B-aligned STS.128
    }
    __syncthreads();

    // ---- Thread tile: 4 half2-cols x 2 row-pairs (rows y,y+1 & y+4,y+5). ----
    const int txg = tid & 15;
    const int tyg = tid >> 4;
    const int oc = txg * 4;                              // tile-local col base
    const int orow = 8 * (tyg >> 1) + 2 * (tyg & 1);     // tile-local row base

    __half2 acc[2][4];
    const __half2 NEG = __float2half2_rn(-60000.0f);
#pragma unroll
    for (int j = 0; j < 2; j++)
#pragma unroll
        for (int c = 0; c < 4; c++) acc[j][c] = NEG;

    subpass<3>(pk, wsh, orow, oc, acc);
    subpass<2>(pk, wsh, orow, oc, acc);
    subpass<1>(pk, wsh, orow, oc, acc);
    subpass<0>(pk, wsh, orow, oc, acc);

    // ---- Store: lane0 -> row y, lane1 -> row y+4; float4 per row (aligned). ----
#pragma unroll
    for (int j = 0; j < 2; j++) {
        const int y0 = ty0 + orow + j;
        const int cg = tx0 + oc;
        float4 lo, hi;
        lo.x = __low2float(acc[j][0]);  lo.y = __low2float(acc[j][1]);
        lo.z = __low2float(acc[j][2]);  lo.w = __low2float(acc[j][3]);
        hi.x = __high2float(acc[j][0]); hi.y = __high2float(acc[j][1]);
        hi.z = __high2float(acc[j][2]); hi.w = __high2float(acc[j][3]);
        *(float4*)&op[y0 * PLANE + cg]       = lo;
        *(float4*)&op[(y0 + 4) * PLANE + cg] = hi;
    }
}

extern "C" void kernel_launch(void* const* d_in, const int* in_sizes, int n_in,
                              void* d_out, int out_size)
{
    const float* x  = (const float*)d_in[0];
    const float* k1 = (const float*)d_in[1];
    const float* k2 = (const float*)d_in[2];
    const float* k3 = (const float*)d_in[3];
    float* out = (float*)d_out;

    (void)in_sizes; (void)n_in; (void)out_size;

    dim3 block(256, 1, 1);
    dim3 grid(PLANE / TW, PLANE / TH, 8 * 64);
    quad_morpho_kernel<<<grid, block>>>(x, k1, k2, k3, out);
}

// round 16
// speedup vs baseline: 1.5433x; 1.0022x over previous
#include <cuda_runtime.h>
#include <cuda_fp16.h>

#define PLANE 256
#define TW 64
#define TH 64
#define PKROWS 66          /* packed rows: pk[r] lanes = (row r-3, row r+1) rel ty0 */
#define SSTRIDE 72         /* half2 per packed row; 288B, 16B-aligned rows */
#define NQ 18              /* column quads per row (72/4) */
#define MAXVAL 10000.0f

__device__ __forceinline__ __half2 h2_from_u32(unsigned u) {
    __half2 h; *(unsigned*)&h = u; return h;
}

__device__ __forceinline__ void load_window(const __half2 (*pk)[SSTRIDE],
                                            int row, int oc, __half2 v[12])
{
    const uint4* rp = (const uint4*)&pk[row][oc];   // 16B-aligned, 3x LDS.128
    uint4 u0 = rp[0], u1 = rp[1], u2 = rp[2];
    v[0] = h2_from_u32(u0.x); v[1]  = h2_from_u32(u0.y);
    v[2] = h2_from_u32(u0.z); v[3]  = h2_from_u32(u0.w);
    v[4] = h2_from_u32(u1.x); v[5]  = h2_from_u32(u1.y);
    v[6] = h2_from_u32(u1.z); v[7]  = h2_from_u32(u1.w);
    v[8] = h2_from_u32(u2.x); v[9]  = h2_from_u32(u2.y);
    v[10]= h2_from_u32(u2.z); v[11] = h2_from_u32(u2.w);
}

__device__ __forceinline__ void load_wrow(const __half2* wsh, int row, __half2 w[8])
{
    uint4 a = *(const uint4*)&wsh[row * 8];        // broadcast LDS.128 x2
    uint4 b = *(const uint4*)&wsh[row * 8 + 4];
    w[0] = h2_from_u32(a.x); w[1] = h2_from_u32(a.y);
    w[2] = h2_from_u32(a.z); w[3] = h2_from_u32(a.w);
    w[4] = h2_from_u32(b.x); w[5] = h2_from_u32(b.y);
    w[6] = h2_from_u32(b.z); w[7] = h2_from_u32(b.w);
}

// 7 taps with weight row w[t] (t increasing with dx). REV=1 uses w[6-t]
// (w(dy,dx) = w(-dy,-dx) mirror). SKIPC=1 skips the center tap (dy==0).
template<int REV, int SKIPC>
__device__ __forceinline__ void taps7(const __half2 v[12], const __half2 w[8],
                                      __half2 acc[4])
{
#pragma unroll
    for (int t = 0; t < 7; t++) {
        if (SKIPC && t == 3) continue;
        const __half2 wv = REV ? w[6 - t] : w[t];
#pragma unroll
        for (int c = 0; c < 4; c++)
            acc[c] = __hmax2(acc[c], __hadd2(v[c + t + 1], wv));
    }
}

// Outer dy group: |dy| in {2,3}. Weight rows for dy=-3,-2 reused (t-reversed)
// for dy=+3,+2. Windows Rr in {0,1,2} and {5,6,7}; only w3,w2 live.
__device__ __forceinline__ void pgroup_outer(const __half2 (*pk)[SSTRIDE],
                                             const __half2* wsh,
                                             int orow, int oc,
                                             __half2 acc[2][4])
{
    __half2 w3[8], w2[8];
    load_wrow(wsh, 0, w3);     // dy = -3
    load_wrow(wsh, 1, w2);     // dy = -2
    __half2 v[12];

    load_window(pk, orow + 0, oc, v);
    taps7<0,0>(v, w3, acc[0]);
    load_window(pk, orow + 1, oc, v);
    taps7<0,0>(v, w2, acc[0]);  taps7<0,0>(v, w3, acc[1]);
    load_window(pk, orow + 2, oc, v);
    taps7<0,0>(v, w2, acc[1]);
    load_window(pk, orow + 5, oc, v);
    taps7<1,0>(v, w2, acc[0]);
    load_window(pk, orow + 6, oc, v);
    taps7<1,0>(v, w3, acc[0]);  taps7<1,0>(v, w2, acc[1]);
    load_window(pk, orow + 7, oc, v);
    taps7<1,0>(v, w3, acc[1]);
}

// Middle dy group: dy in {-1,0,1}; dy=+1 reuses dy=-1 reversed.
// Windows Rr in {2,3,4,5}; only w1,w0 live.
__device__ __forceinline__ void pgroup_mid(const __half2 (*pk)[SSTRIDE],
                                           const __half2* wsh,
                                           int orow, int oc,
                                           __half2 acc[2][4])
{
    __half2 w1[8], w0[8];
    load_wrow(wsh, 2, w1);     // dy = -1
    load_wrow(wsh, 3, w0);     // dy =  0
    __half2 v[12];

    load_window(pk, orow + 2, oc, v);
    taps7<0,0>(v, w1, acc[0]);
    load_window(pk, orow + 3, oc, v);
    taps7<0,1>(v, w0, acc[0]);  taps7<0,0>(v, w1, acc[1]);
    load_window(pk, orow + 4, oc, v);
    taps7<1,0>(v, w1, acc[0]);  taps7<0,1>(v, w0, acc[1]);
    load_window(pk, orow + 5, oc, v);
    taps7<1,0>(v, w1, acc[1]);
}

__global__ __launch_bounds__(256, 6)
void quad_morpho_kernel(const float* __restrict__ x,
                        const float* __restrict__ k1,
                        const float* __restrict__ k2,
                        const float* __restrict__ k3,
                        float* __restrict__ out)
{
    __shared__ alignas(16) __half2 pk[PKROWS][SSTRIDE];
    __shared__ alignas(16) __half2 wsh[4 * 8];   // rows dy=-3,-2,-1,0 (padded to 8)

    const int plane = blockIdx.z;
    const int tx0 = blockIdx.x * TW;
    const int ty0 = blockIdx.y * TH;
    const float* xp = x + (size_t)plane * (PLANE * PLANE);
    float* op = out + (size_t)plane * (PLANE * PLANE);
    const int tid = threadIdx.x;

    // ---- Weight table (dy = -3..0; +dy rows are t-reversed mirrors). Max of
    // the convex-along-axes quadratic over the 7x7 grid is at a corner. ----
    if (tid < 32) {
        const int row = tid >> 3;            // 0..3 -> dy = row - 3
        const int t = tid & 7;               // 0..7 (7 = pad)
        const float A = k1[0], B = k2[0], C = k3[0];
        const float q_pp = 9.0f * A + 18.0f * B + 9.0f * C;
        const float q_pm = 9.0f * A - 18.0f * B + 9.0f * C;
        const float inv_m = 1.0f / fmaxf(q_pp, q_pm);
        const int dy = row - 3;
        const int dx = t - 3;
        float wv = -(A * (float)(dx * dx) + 2.0f * B * (float)(dx * dy)
                     + C * (float)(dy * dy)) * inv_m;
        if (t == 7) wv = 0.0f;               // pad slot
        wsh[tid] = __float2half2_rn(wv);
    }

    // ---- Packed tile fill. smem col c <-> global col tx0 + c - 4 (left halo 4
    // keeps quads 16B-aligned). pk[r][c] = half2(x[ty0+r-3], x[ty0+r+1]). ----
    for (int i = tid; i < PKROWS * NQ; i += 256) {
        const int r = i / NQ;
        const int q = i - r * NQ;
        const int gc = tx0 + q * 4 - 4;
        const int gr0 = ty0 + r - 3;
        const int gr1 = gr0 + 4;
        const bool r0in = (unsigned)gr0 < PLANE;
        const bool r1in = (unsigned)gr1 < PLANE;
        float4 a = make_float4(-MAXVAL, -MAXVAL, -MAXVAL, -MAXVAL);
        float4 b = a;
        if (gc >= 0 && gc <= PLANE - 4) {
            if (r0in) a = *(const float4*)&xp[gr0 * PLANE + gc];
            if (r1in) b = *(const float4*)&xp[gr1 * PLANE + gc];
        } else {
            float* ap = &a.x; float* bp = &b.x;
#pragma unroll
            for (int e = 0; e < 4; e++) {
                const int gce = gc + e;
                if ((unsigned)gce < PLANE) {
                    if (r0in) ap[e] = xp[gr0 * PLANE + gce];
                    if (r1in) bp[e] = xp[gr1 * PLANE + gce];
                }
            }
        }
        __half2 h0 = __floats2half2_rn(a.x, b.x);
        __half2 h1 = __floats2half2_rn(a.y, b.y);
        __half2 h2v = __floats2half2_rn(a.z, b.z);
        __half2 h3 = __floats2half2_rn(a.w, b.w);
        uint4 st;
        st.x = *(unsigned*)&h0; st.y = *(unsigned*)&h1;
        st.z = *(unsigned*)&h2v; st.w = *(unsigned*)&h3;
        *(uint4*)&pk[r][q * 4] = st;       // 16B-aligned STS.128
    }
    __syncthreads();

    // ---- Thread tile: 4 half2-cols x 2 row-pairs (rows y,y+1 & y+4,y+5). ----
    const int txg = tid & 15;
    const int tyg = tid >> 4;
    const int oc = txg * 4;                              // tile-local col base
    const int orow = 8 * (tyg >> 1) + 2 * (tyg & 1);     // tile-local row base

    __half2 acc[2][4];
    const __half2 NEG = __float2half2_rn(-60000.0f);
#pragma unroll
    for (int j = 0; j < 2; j++)
#pragma unroll
        for (int c = 0; c < 4; c++) acc[j][c] = NEG;

    pgroup_outer(pk, wsh, orow, oc, acc);
    pgroup_mid(pk, wsh, orow, oc, acc);

    // ---- Store: lane0 -> row y, lane1 -> row y+4; float4 per row (aligned). ----
#pragma unroll
    for (int j = 0; j < 2; j++) {
        const int y0 = ty0 + orow + j;
        const int cg = tx0 + oc;
        float4 lo, hi;
        lo.x = __low2float(acc[j][0]);  lo.y = __low2float(acc[j][1]);
        lo.z = __low2float(acc[j][2]);  lo.w = __low2float(acc[j][3]);
        hi.x = __high2float(acc[j][0]); hi.y = __high2float(acc[j][1]);
        hi.z = __high2float(acc[j][2]); hi.w = __high2float(acc[j][3]);
        *(float4*)&op[y0 * PLANE + cg]       = lo;
        *(float4*)&op[(y0 + 4) * PLANE + cg] = hi;
    }
}

extern "C" void kernel_launch(void* const* d_in, const int* in_sizes, int n_in,
                              void* d_out, int out_size)
{
    const float* x  = (const float*)d_in[0];
    const float* k1 = (const float*)d_in[1];
    const float* k2 = (const float*)d_in[2];
    const float* k3 = (const float*)d_in[3];
    float* out = (float*)d_out;

    (void)in_sizes; (void)n_in; (void)out_size;

    dim3 block(256, 1, 1);
    dim3 grid(PLANE / TW, PLANE / TH, 8 * 64);
    quad_morpho_kernel<<<grid, block>>>(x, k1, k2, k3, out);
}

// round 17
// speedup vs baseline: 2.2006x; 1.4258x over previous
#include <cuda_runtime.h>
#include <cuda_fp16.h>

#define PLANE 256
#define TW 64
#define TH 64
#define PKROWS 66          /* packed rows: pk[r] lanes = (row r-3, row r+1) rel ty0 */
#define SSTRIDE 72         /* half2 per packed row; 288B, 16B-aligned rows */
#define NQ 18              /* column quads per row (72/4) */
#define MAXVAL 10000.0f

__device__ __forceinline__ __half2 h2_from_u32(unsigned u) {
    __half2 h; *(unsigned*)&h = u; return h;
}

// Phase 1 of a window: v[0..7] (2x LDS.128). Feeds taps t=0..2 (v[1..6]).
__device__ __forceinline__ void win_lo(const __half2 (*pk)[SSTRIDE],
                                       int row, int oc, __half2 v[12])
{
    const uint4* rp = (const uint4*)&pk[row][oc];
    uint4 u0 = rp[0], u1 = rp[1];
    v[0] = h2_from_u32(u0.x); v[1] = h2_from_u32(u0.y);
    v[2] = h2_from_u32(u0.z); v[3] = h2_from_u32(u0.w);
    v[4] = h2_from_u32(u1.x); v[5] = h2_from_u32(u1.y);
    v[6] = h2_from_u32(u1.z); v[7] = h2_from_u32(u1.w);
}

// Phase 2: v[8..11] (1x LDS.128). Feeds taps t=3..6 (v[4..10]).
__device__ __forceinline__ void win_hi(const __half2 (*pk)[SSTRIDE],
                                       int row, int oc, __half2 v[12])
{
    const uint4* rp = (const uint4*)&pk[row][oc];
    uint4 u2 = rp[2];
    v[8]  = h2_from_u32(u2.x); v[9]  = h2_from_u32(u2.y);
    v[10] = h2_from_u32(u2.z); v[11] = h2_from_u32(u2.w);
}

__device__ __forceinline__ void load_wrow(const __half2* wsh, int row, __half2 w[8])
{
    uint4 a = *(const uint4*)&wsh[row * 8];        // broadcast LDS.128 x2
    uint4 b = *(const uint4*)&wsh[row * 8 + 4];
    w[0] = h2_from_u32(a.x); w[1] = h2_from_u32(a.y);
    w[2] = h2_from_u32(a.z); w[3] = h2_from_u32(a.w);
    w[4] = h2_from_u32(b.x); w[5] = h2_from_u32(b.y);
    w[6] = h2_from_u32(b.z); w[7] = h2_from_u32(b.w);
}

// Taps t=0..2 (uses v[1..6]). REV=1 mirrors weights (w(dy,dx)=w(-dy,-dx)).
template<int REV>
__device__ __forceinline__ void taps_lo(const __half2 v[12], const __half2 w[8],
                                        __half2 acc[4])
{
#pragma unroll
    for (int t = 0; t < 3; t++) {
        const __half2 wv = REV ? w[6 - t] : w[t];
#pragma unroll
        for (int c = 0; c < 4; c++)
            acc[c] = __hmax2(acc[c], __hadd2(v[c + t + 1], wv));
    }
}

// Taps t=3..6 (uses v[4..10]). SKIPC=1 skips the center tap (t==3, dy==0 row).
template<int REV, int SKIPC>
__device__ __forceinline__ void taps_hi(const __half2 v[12], const __half2 w[8],
                                        __half2 acc[4])
{
#pragma unroll
    for (int t = 3; t < 7; t++) {
        if (SKIPC && t == 3) continue;
        const __half2 wv = REV ? w[6 - t] : w[t];
#pragma unroll
        for (int c = 0; c < 4; c++)
            acc[c] = __hmax2(acc[c], __hadd2(v[c + t + 1], wv));
    }
}

// Outer dy group: |dy| in {2,3}; dy=+3,+2 reuse dy=-3,-2 rows t-reversed.
// Windows Rr in {0,1,2,5,6,7}, each split lo/hi to cap v-liveness at 8.
__device__ __forceinline__ void pgroup_outer(const __half2 (*pk)[SSTRIDE],
                                             const __half2* wsh,
                                             int orow, int oc,
                                             __half2 acc[2][4])
{
    __half2 w3[8], w2[8];
    load_wrow(wsh, 0, w3);     // dy = -3
    load_wrow(wsh, 1, w2);     // dy = -2
    __half2 v[12];

    win_lo(pk, orow + 0, oc, v);
    taps_lo<0>(v, w3, acc[0]);
    win_hi(pk, orow + 0, oc, v);
    taps_hi<0,0>(v, w3, acc[0]);

    win_lo(pk, orow + 1, oc, v);
    taps_lo<0>(v, w2, acc[0]);  taps_lo<0>(v, w3, acc[1]);
    win_hi(pk, orow + 1, oc, v);
    taps_hi<0,0>(v, w2, acc[0]);  taps_hi<0,0>(v, w3, acc[1]);

    win_lo(pk, orow + 2, oc, v);
    taps_lo<0>(v, w2, acc[1]);
    win_hi(pk, orow + 2, oc, v);
    taps_hi<0,0>(v, w2, acc[1]);

    win_lo(pk, orow + 5, oc, v);
    taps_lo<1>(v, w2, acc[0]);
    win_hi(pk, orow + 5, oc, v);
    taps_hi<1,0>(v, w2, acc[0]);

    win_lo(pk, orow + 6, oc, v);
    taps_lo<1>(v, w3, acc[0]);  taps_lo<1>(v, w2, acc[1]);
    win_hi(pk, orow + 6, oc, v);
    taps_hi<1,0>(v, w3, acc[0]);  taps_hi<1,0>(v, w2, acc[1]);

    win_lo(pk, orow + 7, oc, v);
    taps_lo<1>(v, w3, acc[1]);
    win_hi(pk, orow + 7, oc, v);
    taps_hi<1,0>(v, w3, acc[1]);
}

// Middle dy group: dy in {-1,0,1}; dy=+1 reuses dy=-1 reversed.
// Windows Rr in {2,3,4,5}.
__device__ __forceinline__ void pgroup_mid(const __half2 (*pk)[SSTRIDE],
                                           const __half2* wsh,
                                           int orow, int oc,
                                           __half2 acc[2][4])
{
    __half2 w1[8], w0[8];
    load_wrow(wsh, 2, w1);     // dy = -1
    load_wrow(wsh, 3, w0);     // dy =  0
    __half2 v[12];

    win_lo(pk, orow + 2, oc, v);
    taps_lo<0>(v, w1, acc[0]);
    win_hi(pk, orow + 2, oc, v);
    taps_hi<0,0>(v, w1, acc[0]);

    win_lo(pk, orow + 3, oc, v);
    taps_lo<0>(v, w0, acc[0]);  taps_lo<0>(v, w1, acc[1]);
    win_hi(pk, orow + 3, oc, v);
    taps_hi<0,1>(v, w0, acc[0]);  taps_hi<0,0>(v, w1, acc[1]);

    win_lo(pk, orow + 4, oc, v);
    taps_lo<1>(v, w1, acc[0]);  taps_lo<0>(v, w0, acc[1]);
    win_hi(pk, orow + 4, oc, v);
    taps_hi<1,0>(v, w1, acc[0]);  taps_hi<0,1>(v, w0, acc[1]);

    win_lo(pk, orow + 5, oc, v);
    taps_lo<1>(v, w1, acc[1]);
    win_hi(pk, orow + 5, oc, v);
    taps_hi<1,0>(v, w1, acc[1]);
}

// Bounds-checked float4 row load (fast aligned path; edge quads scalar).
__device__ __forceinline__ float4 load_row4(const float* __restrict__ xp,
                                            int gr, int gc)
{
    float4 t = make_float4(-MAXVAL, -MAXVAL, -MAXVAL, -MAXVAL);
    if ((unsigned)gr < (unsigned)PLANE) {
        if (gc >= 0 && gc <= PLANE - 4) {
            t = *(const float4*)&xp[gr * PLANE + gc];
        } else {
            float* tp = &t.x;
#pragma unroll
            for (int e = 0; e < 4; e++) {
                const int gce = gc + e;
                if ((unsigned)gce < (unsigned)PLANE) tp[e] = xp[gr * PLANE + gce];
            }
        }
    }
    return t;
}

__device__ __forceinline__ uint4 pack_pair(float4 a, float4 b)
{
    __half2 h0 = __floats2half2_rn(a.x, b.x);
    __half2 h1 = __floats2half2_rn(a.y, b.y);
    __half2 h2v = __floats2half2_rn(a.z, b.z);
    __half2 h3 = __floats2half2_rn(a.w, b.w);
    uint4 st;
    st.x = *(unsigned*)&h0; st.y = *(unsigned*)&h1;
    st.z = *(unsigned*)&h2v; st.w = *(unsigned*)&h3;
    return st;
}

__global__ __launch_bounds__(256, 5)
void quad_morpho_kernel(const float* __restrict__ x,
                        const float* __restrict__ k1,
                        const float* __restrict__ k2,
                        const float* __restrict__ k3,
                        float* __restrict__ out)
{
    __shared__ alignas(16) __half2 pk[PKROWS][SSTRIDE];
    __shared__ alignas(16) __half2 wsh[4 * 8];   // rows dy=-3,-2,-1,0 (padded to 8)

    const int plane = blockIdx.z;
    const int tx0 = blockIdx.x * TW;
    const int ty0 = blockIdx.y * TH;
    const float* xp = x + (size_t)plane * (PLANE * PLANE);
    float* op = out + (size_t)plane * (PLANE * PLANE);
    const int tid = threadIdx.x;

    // ---- Weight table (dy = -3..0; +dy rows are t-reversed mirrors). Max of
    // the convex-along-axes quadratic over the 7x7 grid is at a corner. ----
    if (tid < 32) {
        const int row = tid >> 3;            // 0..3 -> dy = row - 3
        const int t = tid & 7;               // 0..7 (7 = pad)
        const float A = k1[0], B = k2[0], C = k3[0];
        const float q_pp = 9.0f * A + 18.0f * B + 9.0f * C;
        const float q_pm = 9.0f * A - 18.0f * B + 9.0f * C;
        const float inv_m = 1.0f / fmaxf(q_pp, q_pm);
        const int dy = row - 3;
        const int dx = t - 3;
        float wv = -(A * (float)(dx * dx) + 2.0f * B * (float)(dx * dy)
                     + C * (float)(dy * dy)) * inv_m;
        if (t == 7) wv = 0.0f;               // pad slot
        wsh[tid] = __float2half2_rn(wv);
    }

    // ---- Packed tile fill with PAIRED rows: each global row is loaded once
    // where possible. Task covers pk[r] and pk[r+4] from 3 global rows
    // (g0, g0+4, g0+8): pk[r]=(g0,g0+4), pk[r+4]=(g0+4,g0+8).
    // Pair bases r in {0..3 mod 8, r<=59} cover pk rows 0..63; pk 64,65 single.
    // smem col c <-> global col tx0 + c - 4 (left halo 4, quads 16B-aligned). ----
    for (int i = tid; i < 34 * NQ; i += 256) {
        const int ru = i / NQ;
        const int q  = i - ru * NQ;
        const bool pair = (ru < 32);
        const int r = pair ? ((ru >> 2) * 8 + (ru & 3)) : (64 + (ru - 32));
        const int gc = tx0 + q * 4 - 4;
        const int g0 = ty0 + r - 3;

        float4 a = load_row4(xp, g0, gc);
        float4 b = load_row4(xp, g0 + 4, gc);
        *(uint4*)&pk[r][q * 4] = pack_pair(a, b);      // 16B-aligned STS.128
        if (pair) {
            float4 c4 = load_row4(xp, g0 + 8, gc);
            *(uint4*)&pk[r + 4][q * 4] = pack_pair(b, c4);
        }
    }
    __syncthreads();

    // ---- Thread tile: 4 half2-cols x 2 row-pairs (rows y,y+1 & y+4,y+5). ----
    const int txg = tid & 15;
    const int tyg = tid >> 4;
    const int oc = txg * 4;                              // tile-local col base
    const int orow = 8 * (tyg >> 1) + 2 * (tyg & 1);     // tile-local row base

    __half2 acc[2][4];
    const __half2 NEG = __float2half2_rn(-60000.0f);
#pragma unroll
    for (int j = 0; j < 2; j++)
#pragma unroll
        for (int c = 0; c < 4; c++) acc[j][c] = NEG;

    pgroup_outer(pk, wsh, orow, oc, acc);
    pgroup_mid(pk, wsh, orow, oc, acc);

    // ---- Store: lane0 -> row y, lane1 -> row y+4; float4 per row (aligned). ----
#pragma unroll
    for (int j = 0; j < 2; j++) {
        const int y0 = ty0 + orow + j;
        const int cg = tx0 + oc;
        float4 lo, hi;
        lo.x = __low2float(acc[j][0]);  lo.y = __low2float(acc[j][1]);
        lo.z = __low2float(acc[j][2]);  lo.w = __low2float(acc[j][3]);
        hi.x = __high2float(acc[j][0]); hi.y = __high2float(acc[j][1]);
        hi.z = __high2float(acc[j][2]); hi.w = __high2float(acc[j][3]);
        *(float4*)&op[y0 * PLANE + cg]       = lo;
        *(float4*)&op[(y0 + 4) * PLANE + cg] = hi;
    }
}

extern "C" void kernel_launch(void* const* d_in, const int* in_sizes, int n_in,
                              void* d_out, int out_size)
{
    const float* x  = (const float*)d_in[0];
    const float* k1 = (const float*)d_in[1];
    const float* k2 = (const float*)d_in[2];
    const float* k3 = (const float*)d_in[3];
    float* out = (float*)d_out;

    (void)in_sizes; (void)n_in; (void)out_size;

    dim3 block(256, 1, 1);
    dim3 grid(PLANE / TW, PLANE / TH, 8 * 64);
    quad_morpho_kernel<<<grid, block>>>(x, k1, k2, k3, out);
}